// round 5
// baseline (speedup 1.0000x reference)
#include <cuda_runtime.h>
#include <math.h>

#define N 8192
#define D 10
#define DD (D * D)
#define TILE 256
#define NT (N / TILE)     // 32 tiles
#define PAD 11
#define NSB (TILE / 32)   // 8 warps / sub-blocks per tile
#define GSTR 260          // Gt row stride (floats): 1040B = 65*16B, float4-safe

// ---- persistent device scratch (no allocation) ----
__device__ float              g_H[NT * DD];
__device__ unsigned int       g_hflag[NT];  // monotone epoch flags
__device__ long long          g_sum  = 0;   // fixed-point accumulator (2^-32)
__device__ unsigned long long g_ctr1 = 0;   // arrival tickets (monotone)
__device__ unsigned long long g_ctr2 = 0;   // finish tickets (monotone)

__device__ __forceinline__ float ex2(float x) {
    float y;
    asm("ex2.approx.ftz.f32 %0, %1;" : "=f"(y) : "f"(x));
    return y;
}
__device__ __forceinline__ float softplus_f(float x) {
    return fmaxf(x, 0.f) + log1pf(expf(-fabsf(x)));
}
__device__ __forceinline__ float decodeT(const int* Tp) {
    int b = *Tp;
    if (b >= 0 && b < (1 << 23)) return (float)b;  // int32 T
    return __int_as_float(b);                      // float32 T
}

__global__ void __launch_bounds__(TILE)
hawkes_fused(const float* __restrict__ t, const int* __restrict__ et,
             const float* __restrict__ mu, const float* __restrict__ la,
             const float* __restrict__ lb, const int* __restrict__ Tp,
             float* __restrict__ out) {
    const int tid = threadIdx.x;
    const int it  = blockIdx.x;

    __shared__ float ts[TILE];
    __shared__ int   es[TILE];
    __shared__ float b2s[DD], abt[DD], alphas[DD], mus[D];
    __shared__ __align__(16) float Gt[D * GSTR];   // transposed G: Gt[k][j]
    __shared__ __align__(16) float F[TILE * PAD];
    __shared__ float subH[NSB][DD];        // per-warp H, then inclusive prefix
    __shared__ unsigned int masks[NSB][D]; // per-(warp, m) membership bitmask
    __shared__ __align__(16) float Psm[D * PAD];
    __shared__ float trefs[NT];
    __shared__ double red[NSB];
    __shared__ unsigned long long tick_s;

    // ---- grab ticket immediately (epoch known early) ----
    if (tid == 0) tick_s = atomicAdd(&g_ctr1, 1ULL);

    // ---- tables + tile load + tref gather ----
    if (tid < DD) {
        float a = softplus_f(la[tid]);
        float b = softplus_f(lb[tid]);
        alphas[tid] = a;
        b2s[tid]    = b * 1.4426950408889634f;
        abt[tid]    = a * b;
    }
    if (tid >= 128 && tid < 128 + D) mus[tid - 128] = softplus_f(mu[tid - 128]);
    if (tid >= 160 && tid < 160 + NT) trefs[tid - 160] = t[(tid - 160) * TILE + TILE - 1];

    const int i = it * TILE + tid;
    ts[tid] = t[i];
    es[tid] = et[i];
    __syncthreads();

    const float tref = trefs[it];
    const float ti   = ts[tid];
    const int   ei   = es[tid];
    const float dtj  = ti - tref;   // <= 0

    // Gt[k][tid] = 2^(b2[k][e_i]*(t_i - tref)) <= 1
#pragma unroll
    for (int k = 0; k < D; k++)
        Gt[k * GSTR + tid] = ex2(b2s[k * D + ei] * dtj);

    // per-warp membership bitmasks
    {
        const int lane = tid & 31, w = tid >> 5;
#pragma unroll
        for (int m = 0; m < D; m++) {
            unsigned b = __ballot_sync(0xffffffffu, ei == m);
            if (lane == m) masks[w][m] = b;
        }
    }
    __syncthreads();

    // ---- subH[sb][m][k] = sum_{j in sb, e_j=m} Gt[k][j]  (LDS.128 + mask) ----
    for (int e = tid; e < NSB * DD; e += TILE) {
        const int sb = e / DD, r = e - sb * DD;
        const int m = r / D, kk = r - m * D;
        const unsigned msk = masks[sb][m];
        const float* row = &Gt[kk * GSTR + sb * 32];
        float acc = 0.f;
#pragma unroll
        for (int q = 0; q < 8; q++) {
            float4 v = *(const float4*)(row + q * 4);
            acc += (msk & (1u << (q * 4 + 0))) ? v.x : 0.f;
            acc += (msk & (1u << (q * 4 + 1))) ? v.y : 0.f;
            acc += (msk & (1u << (q * 4 + 2))) ? v.z : 0.f;
            acc += (msk & (1u << (q * 4 + 3))) ? v.w : 0.f;
        }
        subH[sb][r] = acc;
    }
    __syncthreads();

    // ---- inclusive prefix over sub-blocks + EARLY publish of full-tile H ----
    if (tid < DD) {
        float run = subH[0][tid];
#pragma unroll
        for (int sb = 1; sb < NSB; sb++) { run += subH[sb][tid]; subH[sb][tid] = run; }
        g_H[it * DD + tid] = run;
        __threadfence();   // release H
    }
    __syncthreads();
    const unsigned int epoch1 = (unsigned int)(tick_s / NT) + 1u;
    if (tid == 0) atomicExch(&g_hflag[it], epoch1);

    // ---- local work (overlaps peers' spins): F, triangle, crossSub ----
#pragma unroll
    for (int m = 0; m < D; m++)
        F[tid * PAD + m] = abt[ei * D + m] * ex2(-b2s[ei * D + m] * dtj);
    __syncthreads();

    float tri = 0.f;
    {
        const int base = tid & ~31;
        const int lid  = tid & 31;
#pragma unroll
        for (int jj = 0; jj < 31; jj++) {
            if (jj < lid) {
                int j  = base + jj;
                int ej = es[j];
                tri = fmaf(F[tid * PAD + ej], Gt[ei * GSTR + j], tri);
            }
        }
    }

    float crossSub = 0.f;
    {
        const int sb = tid >> 5;
        if (sb > 0) {
#pragma unroll
            for (int m = 0; m < D; m++)
                crossSub = fmaf(F[tid * PAD + m], subH[sb - 1][m * D + ei], crossSub);
        }
    }

    // ---- spin on predecessors ----
    if (tid < it) {
        while (*(volatile unsigned int*)&g_hflag[tid] < epoch1)
            __nanosleep(32);
    }
    __syncthreads();
    __threadfence();   // acquire H

    // ---- cross-tile P: fully unrolled, predicated -> high MLP ----
    if (tid < DD) {
        const int m = tid / D, kk = tid % D;
        const float b2 = b2s[kk * D + m];
        float acc = 0.f;
#pragma unroll
        for (int s = 0; s < NT - 1; s++) {
            if (s < it) {
                float Hs = __ldcg(&g_H[s * DD + tid]);
                acc = fmaf(Hs, ex2(-b2 * (tref - trefs[s])), acc);
            }
        }
        Psm[m * PAD + kk] = acc;
    }
    __syncthreads();

    float crossTile = 0.f;
    if (it > 0) {
#pragma unroll
        for (int m = 0; m < D; m++)
            crossTile = fmaf(F[tid * PAD + m], Psm[m * PAD + ei], crossTile);
    }

    // ---- finalize per event ----
    const float Tf    = decodeT(Tp);
    const float inten = mus[ei] + tri + crossSub + crossTile;
    const float dT    = Tf - ti;
    float contrib = 0.f;
#pragma unroll
    for (int d = 0; d < D; d++)
        contrib += alphas[d * D + ei] * (1.f - ex2(-b2s[d * D + ei] * dT));

    double v = (double)__logf(inten) - (double)contrib;

    // ---- warp-shuffle double reduction ----
#pragma unroll
    for (int off = 16; off > 0; off >>= 1)
        v += __shfl_down_sync(0xffffffffu, v, off);
    if ((tid & 31) == 0) red[tid >> 5] = v;
    __syncthreads();

    if (tid == 0) {
        double bs = 0.0;
#pragma unroll
        for (int w = 0; w < NSB; w++) bs += red[w];
        long long q = __double2ll_rn(bs * 4294967296.0);
        atomicAdd((unsigned long long*)&g_sum, (unsigned long long)q);
        __threadfence();
        unsigned long long t2 = atomicAdd(&g_ctr2, 1ULL);
        if ((t2 % NT) == (NT - 1)) {
            __threadfence();
            long long tot = (long long)atomicExch((unsigned long long*)&g_sum, 0ULL);
            double s = (double)tot / 4294967296.0;
            double musum = 0.0;
#pragma unroll
            for (int d = 0; d < D; d++) musum += (double)mus[d];
            out[0] = (float)(s - musum * (double)Tf);
        }
    }
}

extern "C" void kernel_launch(void* const* d_in, const int* in_sizes, int n_in,
                              void* d_out, int out_size) {
    const float* t  = (const float*)d_in[0];
    const int*   et = (const int*)d_in[1];
    const float* mu = (const float*)d_in[2];
    const float* la = (const float*)d_in[3];
    const float* lb = (const float*)d_in[4];
    const int*   Tp = (const int*)d_in[5];

    hawkes_fused<<<NT, TILE>>>(t, et, mu, la, lb, Tp, (float*)d_out);
}